// round 7
// baseline (speedup 1.0000x reference)
#include <cuda_runtime.h>
#include <stdint.h>

#define HIDDEN 128
#define NRAD   6
#define WARPS  8        // per block (256 threads)
#define STAGES 4        // cp.async pipeline depth per warp

__global__ void zero_out_kernel(float4* __restrict__ out, int n4) {
    int idx = blockIdx.x * blockDim.x + threadIdx.x;
    int stride = gridDim.x * blockDim.x;
    for (int k = idx; k < n4; k += stride)
        out[k] = make_float4(0.f, 0.f, 0.f, 0.f);
}

__device__ __forceinline__ uint32_t smem_u32(const void* p) {
    uint32_t a;
    asm("{ .reg .u64 t; cvta.to.shared.u64 t, %1; cvt.u32.u64 %0, t; }"
        : "=r"(a) : "l"(p));
    return a;
}
__device__ __forceinline__ void cp_async16(uint32_t dst, const void* src) {
    asm volatile("cp.async.cg.shared.global [%0], [%1], 16;" :: "r"(dst), "l"(src));
}
__device__ __forceinline__ void cp_async8(uint32_t dst, const void* src) {
    asm volatile("cp.async.ca.shared.global [%0], [%1], 8;" :: "r"(dst), "l"(src));
}
__device__ __forceinline__ void cp_commit() {
    asm volatile("cp.async.commit_group;" ::: "memory");
}
__device__ __forceinline__ void cp_wait3() {
    asm volatile("cp.async.wait_group 3;" ::: "memory");
}

// Per-warp cp.async pipeline: each warp owns a contiguous chunk of edge PAIRS.
// Stage = one pair: 2 x-rows (1KB) + rbf (48B) + idx (8B) staged in smem.
// W register-resident; lane owns channels [4*lane, 4*lane+4).
__global__ void __launch_bounds__(256, 5)
fused_rbf_scatter_kernel(const float* __restrict__ x,
                         const float* __restrict__ rbf,
                         const float* __restrict__ W,
                         const int* __restrict__ idx,
                         float* __restrict__ out,
                         int E)
{
    __shared__ float4 sX[WARPS][STAGES][2][32];  // [warp][stage][edge][lane]
    __shared__ float4 sR[WARPS][STAGES][3];      // pair rbf rows (48B)
    __shared__ int2   sI[WARPS][STAGES];         // pair node indices

    const int lane = threadIdx.x & 31;
    const int w    = threadIdx.x >> 5;
    const int wid  = (blockIdx.x * blockDim.x + threadIdx.x) >> 5;
    const int nwarp = (gridDim.x * blockDim.x) >> 5;

    // This lane's 4 rows of W (24 floats) in registers.
    const int hbase = lane * 4;
    float w00,w01,w02,w03,w04,w05;
    float w10,w11,w12,w13,w14,w15;
    float w20,w21,w22,w23,w24,w25;
    float w30,w31,w32,w33,w34,w35;
    {
        const float* p = W + hbase * NRAD;
        w00=p[0];  w01=p[1];  w02=p[2];  w03=p[3];  w04=p[4];  w05=p[5];
        w10=p[6];  w11=p[7];  w12=p[8];  w13=p[9];  w14=p[10]; w15=p[11];
        w20=p[12]; w21=p[13]; w22=p[14]; w23=p[15]; w24=p[16]; w25=p[17];
        w30=p[18]; w31=p[19]; w32=p[20]; w33=p[21]; w34=p[22]; w35=p[23];
    }

    const float4* __restrict__ x4   = reinterpret_cast<const float4*>(x);
    const float4* __restrict__ rbf4 = reinterpret_cast<const float4*>(rbf);
    const int2*   __restrict__ idx2 = reinterpret_cast<const int2*>(idx);

    const int pairs = E >> 1;
    const int chunk = (pairs + nwarp - 1) / nwarp;
    const int p0    = wid * chunk;
    int pend = p0 + chunk;
    if (pend > pairs) pend = pairs;
    const int np = pend - p0;

    const uint32_t sx_base = smem_u32(&sX[w][0][0][0]);
    const uint32_t sr_base = smem_u32(&sR[w][0][0]);
    const uint32_t si_base = smem_u32(&sI[w][0]);

    // issue stage i (relative pair index); always commits a group
#define ISSUE_STAGE(i)                                                          \
    do {                                                                        \
        int _i = (i);                                                           \
        if (_i < np) {                                                          \
            int _s = _i & (STAGES - 1);                                         \
            size_t _p = (size_t)(p0 + _i);                                      \
            cp_async16(sx_base + (uint32_t)(_s * 1024 + lane * 16),             \
                       x4 + 2 * _p * (HIDDEN / 4) + lane);                      \
            cp_async16(sx_base + (uint32_t)(_s * 1024 + 512 + lane * 16),       \
                       x4 + (2 * _p + 1) * (HIDDEN / 4) + lane);                \
            if (lane < 3)                                                       \
                cp_async16(sr_base + (uint32_t)(_s * 48 + lane * 16),           \
                           rbf4 + 3 * _p + lane);                               \
            else if (lane == 3)                                                 \
                cp_async8(si_base + (uint32_t)(_s * 8), idx2 + _p);             \
        }                                                                       \
        cp_commit();                                                            \
    } while (0)

    if (np > 0) {
        // prologue: stages 0..2 in flight
        ISSUE_STAGE(0);
        ISSUE_STAGE(1);
        ISSUE_STAGE(2);

        for (int i = 0; i < np; ++i) {
            ISSUE_STAGE(i + 3);
            cp_wait3();            // stage i's group complete (3 younger pending)
            __syncwarp();          // make peer lanes' copies visible

            const int s = i & (STAGES - 1);
            float4 f0 = sR[w][s][0];
            float4 f1 = sR[w][s][1];
            float4 f2 = sR[w][s][2];
            int2 nodes = sI[w][s];

            // edge0: rbf = {f0.x,f0.y,f0.z,f0.w,f1.x,f1.y}
            float4 xv0 = sX[w][s][0][lane];
            float c0 = fmaf(f0.x, w00, fmaf(f0.y, w01, fmaf(f0.z, w02,
                       fmaf(f0.w, w03, fmaf(f1.x, w04, f1.y * w05)))));
            float c1 = fmaf(f0.x, w10, fmaf(f0.y, w11, fmaf(f0.z, w12,
                       fmaf(f0.w, w13, fmaf(f1.x, w14, f1.y * w15)))));
            float c2 = fmaf(f0.x, w20, fmaf(f0.y, w21, fmaf(f0.z, w22,
                       fmaf(f0.w, w23, fmaf(f1.x, w24, f1.y * w25)))));
            float c3 = fmaf(f0.x, w30, fmaf(f0.y, w31, fmaf(f0.z, w32,
                       fmaf(f0.w, w33, fmaf(f1.x, w34, f1.y * w35)))));
            float* dst0 = out + (size_t)nodes.x * HIDDEN + hbase;
            asm volatile("red.global.add.v4.f32 [%0], {%1, %2, %3, %4};"
                         :: "l"(dst0), "f"(c0 * xv0.x), "f"(c1 * xv0.y),
                            "f"(c2 * xv0.z), "f"(c3 * xv0.w) : "memory");

            // edge1: rbf = {f1.z,f1.w,f2.x,f2.y,f2.z,f2.w}
            float4 xv1 = sX[w][s][1][lane];
            float d0 = fmaf(f1.z, w00, fmaf(f1.w, w01, fmaf(f2.x, w02,
                       fmaf(f2.y, w03, fmaf(f2.z, w04, f2.w * w05)))));
            float d1 = fmaf(f1.z, w10, fmaf(f1.w, w11, fmaf(f2.x, w12,
                       fmaf(f2.y, w13, fmaf(f2.z, w14, f2.w * w15)))));
            float d2 = fmaf(f1.z, w20, fmaf(f1.w, w21, fmaf(f2.x, w22,
                       fmaf(f2.y, w23, fmaf(f2.z, w24, f2.w * w25)))));
            float d3 = fmaf(f1.z, w30, fmaf(f1.w, w31, fmaf(f2.x, w32,
                       fmaf(f2.y, w33, fmaf(f2.z, w34, f2.w * w35)))));
            float* dst1 = out + (size_t)nodes.y * HIDDEN + hbase;
            asm volatile("red.global.add.v4.f32 [%0], {%1, %2, %3, %4};"
                         :: "l"(dst1), "f"(d0 * xv1.x), "f"(d1 * xv1.y),
                            "f"(d2 * xv1.z), "f"(d3 * xv1.w) : "memory");
        }
    }
#undef ISSUE_STAGE

    // Odd tail edge (E odd): global warp 0 handles it.
    if ((E & 1) && wid == 0) {
        const int e = E - 1;
        int node = idx[e];
        const float2* r2 = reinterpret_cast<const float2*>(rbf) + 3 * (size_t)e;
        float2 g0 = r2[0], g1 = r2[1], g2 = r2[2];
        float4 xv = x4[(size_t)e * (HIDDEN / 4) + lane];

        float c0 = fmaf(g0.x, w00, fmaf(g0.y, w01, fmaf(g1.x, w02,
                   fmaf(g1.y, w03, fmaf(g2.x, w04, g2.y * w05)))));
        float c1 = fmaf(g0.x, w10, fmaf(g0.y, w11, fmaf(g1.x, w12,
                   fmaf(g1.y, w13, fmaf(g2.x, w14, g2.y * w15)))));
        float c2 = fmaf(g0.x, w20, fmaf(g0.y, w21, fmaf(g1.x, w22,
                   fmaf(g1.y, w23, fmaf(g2.x, w24, g2.y * w25)))));
        float c3 = fmaf(g0.x, w30, fmaf(g0.y, w31, fmaf(g1.x, w32,
                   fmaf(g1.y, w33, fmaf(g2.x, w34, g2.y * w35)))));

        float* dst = out + (size_t)node * HIDDEN + hbase;
        asm volatile("red.global.add.v4.f32 [%0], {%1, %2, %3, %4};"
                     :: "l"(dst), "f"(c0 * xv.x), "f"(c1 * xv.y),
                        "f"(c2 * xv.z), "f"(c3 * xv.w) : "memory");
    }
}

extern "C" void kernel_launch(void* const* d_in, const int* in_sizes, int n_in,
                              void* d_out, int out_size)
{
    const float* x   = (const float*)d_in[0];   // [E, 128]
    const float* rbf = (const float*)d_in[1];   // [E, 6]
    const float* W   = (const float*)d_in[2];   // [128, 6]
    const int*   idx = (const int*)d_in[3];     // [E] int32
    float*       out = (float*)d_out;           // [num_nodes, 128]

    const int E = in_sizes[0] / HIDDEN;

    // Zero output (poisoned to 0xAA by harness)
    {
        int n4 = out_size / 4;
        int threads = 256;
        int blocks = (n4 + threads - 1) / threads;
        if (blocks > 8192) blocks = 8192;
        zero_out_kernel<<<blocks, threads>>>((float4*)out, n4);
    }

    // Fused compute + scatter-add: per-warp cp.async pipeline.
    {
        int threads = 256;                  // 8 warps
        int blocks  = 148 * 5;              // 740 CTAs -> 5920 warps
        int pairs = (E >> 1) > 0 ? (E >> 1) : 1;
        int max_blocks = (pairs + WARPS - 1) / WARPS;
        if (blocks > max_blocks) blocks = max_blocks;
        fused_rbf_scatter_kernel<<<blocks, threads>>>(x, rbf, W, idx, out, E);
    }
}

// round 9
// speedup vs baseline: 1.0783x; 1.0783x over previous
#include <cuda_runtime.h>
#include <stdint.h>

#define HIDDEN 128
#define NRAD   6
#define WARPS  8        // per block (256 threads)
#define STAGES 4        // cp.async pipeline depth per warp

__global__ void zero_out_kernel(float4* __restrict__ out, int n4) {
    int idx = blockIdx.x * blockDim.x + threadIdx.x;
    int stride = gridDim.x * blockDim.x;
    for (int k = idx; k < n4; k += stride)
        out[k] = make_float4(0.f, 0.f, 0.f, 0.f);
}

__device__ __forceinline__ uint32_t smem_u32(const void* p) {
    uint32_t a;
    asm("{ .reg .u64 t; cvta.to.shared.u64 t, %1; cvt.u32.u64 %0, t; }"
        : "=r"(a) : "l"(p));
    return a;
}
// evict_first policy: streaming data must not displace the L2-resident output
__device__ __forceinline__ uint64_t mk_policy() {
    uint64_t pol;
    asm("createpolicy.fractional.L2::evict_first.b64 %0, 1.0;" : "=l"(pol));
    return pol;
}
__device__ __forceinline__ void cp_async16_ef(uint32_t dst, const void* src, uint64_t pol) {
    asm volatile("cp.async.cg.shared.global.L2::cache_hint [%0], [%1], 16, %2;"
                 :: "r"(dst), "l"(src), "l"(pol));
}
__device__ __forceinline__ void cp_async8_ef(uint32_t dst, const void* src, uint64_t pol) {
    asm volatile("cp.async.ca.shared.global.L2::cache_hint [%0], [%1], 8, %2;"
                 :: "r"(dst), "l"(src), "l"(pol));
}
__device__ __forceinline__ void cp_commit() {
    asm volatile("cp.async.commit_group;" ::: "memory");
}
__device__ __forceinline__ void cp_wait3() {
    asm volatile("cp.async.wait_group 3;" ::: "memory");
}

// Per-warp cp.async pipeline: each warp owns a contiguous chunk of edge PAIRS.
// Stage = one pair: 2 x-rows (1KB) + rbf (48B) + idx (8B) staged in smem.
// All streaming loads carry L2::evict_first so the atomic output stays L2-resident.
__global__ void __launch_bounds__(256, 5)
fused_rbf_scatter_kernel(const float* __restrict__ x,
                         const float* __restrict__ rbf,
                         const float* __restrict__ W,
                         const int* __restrict__ idx,
                         float* __restrict__ out,
                         int E)
{
    __shared__ float4 sX[WARPS][STAGES][2][32];  // [warp][stage][edge][lane]
    __shared__ float4 sR[WARPS][STAGES][3];      // pair rbf rows (48B)
    __shared__ int2   sI[WARPS][STAGES];         // pair node indices

    const int lane = threadIdx.x & 31;
    const int w    = threadIdx.x >> 5;
    const int wid  = (blockIdx.x * blockDim.x + threadIdx.x) >> 5;
    const int nwarp = (gridDim.x * blockDim.x) >> 5;

    const uint64_t pol = mk_policy();

    // This lane's 4 rows of W (24 floats) in registers.
    const int hbase = lane * 4;
    float w00,w01,w02,w03,w04,w05;
    float w10,w11,w12,w13,w14,w15;
    float w20,w21,w22,w23,w24,w25;
    float w30,w31,w32,w33,w34,w35;
    {
        const float* p = W + hbase * NRAD;
        w00=p[0];  w01=p[1];  w02=p[2];  w03=p[3];  w04=p[4];  w05=p[5];
        w10=p[6];  w11=p[7];  w12=p[8];  w13=p[9];  w14=p[10]; w15=p[11];
        w20=p[12]; w21=p[13]; w22=p[14]; w23=p[15]; w24=p[16]; w25=p[17];
        w30=p[18]; w31=p[19]; w32=p[20]; w33=p[21]; w34=p[22]; w35=p[23];
    }

    const float4* __restrict__ x4   = reinterpret_cast<const float4*>(x);
    const float4* __restrict__ rbf4 = reinterpret_cast<const float4*>(rbf);
    const int2*   __restrict__ idx2 = reinterpret_cast<const int2*>(idx);

    const int pairs = E >> 1;
    const int chunk = (pairs + nwarp - 1) / nwarp;
    const int p0    = wid * chunk;
    int pend = p0 + chunk;
    if (pend > pairs) pend = pairs;
    const int np = pend - p0;

    const uint32_t sx_base = smem_u32(&sX[w][0][0][0]);
    const uint32_t sr_base = smem_u32(&sR[w][0][0]);
    const uint32_t si_base = smem_u32(&sI[w][0]);

#define ISSUE_STAGE(i)                                                          \
    do {                                                                        \
        int _i = (i);                                                           \
        if (_i < np) {                                                          \
            int _s = _i & (STAGES - 1);                                         \
            size_t _p = (size_t)(p0 + _i);                                      \
            cp_async16_ef(sx_base + (uint32_t)(_s * 1024 + lane * 16),          \
                          x4 + 2 * _p * (HIDDEN / 4) + lane, pol);              \
            cp_async16_ef(sx_base + (uint32_t)(_s * 1024 + 512 + lane * 16),    \
                          x4 + (2 * _p + 1) * (HIDDEN / 4) + lane, pol);        \
            if (lane < 3)                                                       \
                cp_async16_ef(sr_base + (uint32_t)(_s * 48 + lane * 16),        \
                              rbf4 + 3 * _p + lane, pol);                       \
            else if (lane == 3)                                                 \
                cp_async8_ef(si_base + (uint32_t)(_s * 8), idx2 + _p, pol);     \
        }                                                                       \
        cp_commit();                                                            \
    } while (0)

    if (np > 0) {
        ISSUE_STAGE(0);
        ISSUE_STAGE(1);
        ISSUE_STAGE(2);

        for (int i = 0; i < np; ++i) {
            ISSUE_STAGE(i + 3);
            cp_wait3();            // stage i complete (3 younger groups pending)
            __syncwarp();

            const int s = i & (STAGES - 1);
            float4 f0 = sR[w][s][0];
            float4 f1 = sR[w][s][1];
            float4 f2 = sR[w][s][2];
            int2 nodes = sI[w][s];

            // edge0: rbf = {f0.x,f0.y,f0.z,f0.w,f1.x,f1.y}
            float4 xv0 = sX[w][s][0][lane];
            float c0 = fmaf(f0.x, w00, fmaf(f0.y, w01, fmaf(f0.z, w02,
                       fmaf(f0.w, w03, fmaf(f1.x, w04, f1.y * w05)))));
            float c1 = fmaf(f0.x, w10, fmaf(f0.y, w11, fmaf(f0.z, w12,
                       fmaf(f0.w, w13, fmaf(f1.x, w14, f1.y * w15)))));
            float c2 = fmaf(f0.x, w20, fmaf(f0.y, w21, fmaf(f0.z, w22,
                       fmaf(f0.w, w23, fmaf(f1.x, w24, f1.y * w25)))));
            float c3 = fmaf(f0.x, w30, fmaf(f0.y, w31, fmaf(f0.z, w32,
                       fmaf(f0.w, w33, fmaf(f1.x, w34, f1.y * w35)))));
            float* dst0 = out + (size_t)nodes.x * HIDDEN + hbase;
            asm volatile("red.global.add.v4.f32 [%0], {%1, %2, %3, %4};"
                         :: "l"(dst0), "f"(c0 * xv0.x), "f"(c1 * xv0.y),
                            "f"(c2 * xv0.z), "f"(c3 * xv0.w) : "memory");

            // edge1: rbf = {f1.z,f1.w,f2.x,f2.y,f2.z,f2.w}
            float4 xv1 = sX[w][s][1][lane];
            float d0 = fmaf(f1.z, w00, fmaf(f1.w, w01, fmaf(f2.x, w02,
                       fmaf(f2.y, w03, fmaf(f2.z, w04, f2.w * w05)))));
            float d1 = fmaf(f1.z, w10, fmaf(f1.w, w11, fmaf(f2.x, w12,
                       fmaf(f2.y, w13, fmaf(f2.z, w14, f2.w * w15)))));
            float d2 = fmaf(f1.z, w20, fmaf(f1.w, w21, fmaf(f2.x, w22,
                       fmaf(f2.y, w23, fmaf(f2.z, w24, f2.w * w25)))));
            float d3 = fmaf(f1.z, w30, fmaf(f1.w, w31, fmaf(f2.x, w32,
                       fmaf(f2.y, w33, fmaf(f2.z, w34, f2.w * w35)))));
            float* dst1 = out + (size_t)nodes.y * HIDDEN + hbase;
            asm volatile("red.global.add.v4.f32 [%0], {%1, %2, %3, %4};"
                         :: "l"(dst1), "f"(d0 * xv1.x), "f"(d1 * xv1.y),
                            "f"(d2 * xv1.z), "f"(d3 * xv1.w) : "memory");
        }
    }
#undef ISSUE_STAGE

    // Odd tail edge (E odd): global warp 0 handles it.
    if ((E & 1) && wid == 0) {
        const int e = E - 1;
        int node = idx[e];
        const float2* r2 = reinterpret_cast<const float2*>(rbf) + 3 * (size_t)e;
        float2 g0 = r2[0], g1 = r2[1], g2 = r2[2];
        float4 xv = x4[(size_t)e * (HIDDEN / 4) + lane];

        float c0 = fmaf(g0.x, w00, fmaf(g0.y, w01, fmaf(g1.x, w02,
                   fmaf(g1.y, w03, fmaf(g2.x, w04, g2.y * w05)))));
        float c1 = fmaf(g0.x, w10, fmaf(g0.y, w11, fmaf(g1.x, w12,
                   fmaf(g1.y, w13, fmaf(g2.x, w14, g2.y * w15)))));
        float c2 = fmaf(g0.x, w20, fmaf(g0.y, w21, fmaf(g1.x, w22,
                   fmaf(g1.y, w23, fmaf(g2.x, w24, g2.y * w25)))));
        float c3 = fmaf(g0.x, w30, fmaf(g0.y, w31, fmaf(g1.x, w32,
                   fmaf(g1.y, w33, fmaf(g2.x, w34, g2.y * w35)))));

        float* dst = out + (size_t)node * HIDDEN + hbase;
        asm volatile("red.global.add.v4.f32 [%0], {%1, %2, %3, %4};"
                     :: "l"(dst), "f"(c0 * xv.x), "f"(c1 * xv.y),
                        "f"(c2 * xv.z), "f"(c3 * xv.w) : "memory");
    }
}

extern "C" void kernel_launch(void* const* d_in, const int* in_sizes, int n_in,
                              void* d_out, int out_size)
{
    const float* x   = (const float*)d_in[0];   // [E, 128]
    const float* rbf = (const float*)d_in[1];   // [E, 6]
    const float* W   = (const float*)d_in[2];   // [128, 6]
    const int*   idx = (const int*)d_in[3];     // [E] int32
    float*       out = (float*)d_out;           // [num_nodes, 128]

    const int E = in_sizes[0] / HIDDEN;

    // Zero output (poisoned to 0xAA by harness)
    {
        int n4 = out_size / 4;
        int threads = 256;
        int blocks = (n4 + threads - 1) / threads;
        if (blocks > 8192) blocks = 8192;
        zero_out_kernel<<<blocks, threads>>>((float4*)out, n4);
    }

    // Fused compute + scatter-add: per-warp cp.async pipeline + evict_first.
    {
        int threads = 256;                  // 8 warps
        int blocks  = 148 * 5;              // 740 CTAs -> 5920 warps
        int pairs = (E >> 1) > 0 ? (E >> 1) : 1;
        int max_blocks = (pairs + WARPS - 1) / WARPS;
        if (blocks > max_blocks) blocks = max_blocks;
        fused_rbf_scatter_kernel<<<blocks, threads>>>(x, rbf, W, idx, out, E);
    }
}

// round 10
// speedup vs baseline: 1.2369x; 1.1471x over previous
#include <cuda_runtime.h>
#include <stdint.h>

#define HIDDEN  128
#define NRAD    6
#define TILE_G  32          // groups per smem tile (1 group = 4 edges)
#define THREADS 128

__global__ void zero_out_kernel(float4* __restrict__ out, int n4) {
    int idx = blockIdx.x * blockDim.x + threadIdx.x;
    int stride = gridDim.x * blockDim.x;
    for (int k = idx; k < n4; k += stride)
        out[k] = make_float4(0.f, 0.f, 0.f, 0.f);
}

__device__ __forceinline__ uint32_t smem_u32(const void* p) {
    uint32_t a;
    asm("{ .reg .u64 t; cvta.to.shared.u64 t, %1; cvt.u32.u64 %0, t; }"
        : "=r"(a) : "l"(p));
    return a;
}
__device__ __forceinline__ uint64_t mk_policy() {
    uint64_t pol;
    asm("createpolicy.fractional.L2::evict_first.b64 %0, 1.0;" : "=l"(pol));
    return pol;
}
__device__ __forceinline__ void cp16_ef(uint32_t dst, const void* src, uint64_t pol) {
    asm volatile("cp.async.cg.shared.global.L2::cache_hint [%0], [%1], 16, %2;"
                 :: "r"(dst), "l"(src), "l"(pol));
}
__device__ __forceinline__ void cp_commit() {
    asm volatile("cp.async.commit_group;" ::: "memory");
}
__device__ __forceinline__ void cp_wait1() {
    asm volatile("cp.async.wait_group 1;" ::: "memory");
}

// Groups of 4 edges. Warp w handles groups g = C0 + w + 4k (k = 0,1,2,...).
// rbf+idx staged per-CTA in double-buffered smem tiles (cp.async, evict_first).
// x rows register-prefetched one group ahead (__ldcs). W register-resident.
__global__ void __launch_bounds__(THREADS, 6)
fused_rbf_scatter_kernel(const float* __restrict__ x,
                         const float* __restrict__ rbf,
                         const float* __restrict__ W,
                         const int* __restrict__ idx,
                         float* __restrict__ out,
                         int E)
{
    __shared__ float4 sRbf[2][TILE_G * 6];   // 24 floats per group
    __shared__ int4   sIdx[2][TILE_G];       // 4 node indices per group

    const int tid  = threadIdx.x;
    const int lane = tid & 31;
    const int w    = tid >> 5;               // warp in block, 0..3

    const uint64_t pol = mk_policy();

    // ---- W: this lane's 4 channel rows, 24 floats in registers ----
    const int hbase = lane * 4;
    float w00,w01,w02,w03,w04,w05;
    float w10,w11,w12,w13,w14,w15;
    float w20,w21,w22,w23,w24,w25;
    float w30,w31,w32,w33,w34,w35;
    {
        const float* p = W + hbase * NRAD;
        w00=p[0];  w01=p[1];  w02=p[2];  w03=p[3];  w04=p[4];  w05=p[5];
        w10=p[6];  w11=p[7];  w12=p[8];  w13=p[9];  w14=p[10]; w15=p[11];
        w20=p[12]; w21=p[13]; w22=p[14]; w23=p[15]; w24=p[16]; w25=p[17];
        w30=p[18]; w31=p[19]; w32=p[20]; w33=p[21]; w34=p[22]; w35=p[23];
    }

    const float4* __restrict__ x4   = reinterpret_cast<const float4*>(x);
    const float4* __restrict__ rbf4 = reinterpret_cast<const float4*>(rbf);
    const int4*   __restrict__ idx4 = reinterpret_cast<const int4*>(idx);

    const int G     = E >> 2;                // full 4-edge groups
    const int nb    = gridDim.x;
    const int chunk = (G + nb - 1) / nb;
    const int C0    = blockIdx.x * chunk;
    int C1 = C0 + chunk; if (C1 > G) C1 = G;

    if (C0 < C1) {
        const int np     = C1 - C0;
        const int ntiles = (np + TILE_G - 1) / TILE_G;

        const uint32_t srbf0 = smem_u32(&sRbf[0][0]);
        const uint32_t sidx0 = smem_u32(&sIdx[0][0]);

        // cooperative issue of tile t into buffer t&1 (always commits a group)
        auto issue_tile = [&](int t) {
            if (t < ntiles) {
                const int base = C0 + t * TILE_G;
                int ts = C1 - base; if (ts > TILE_G) ts = TILE_G;
                const int bb = t & 1;
                const int nr = ts * 6;                       // rbf float4 count
                const uint32_t rb = srbf0 + bb * (TILE_G * 6 * 16);
                const uint32_t ib = sidx0 + bb * (TILE_G * 16);
                if (tid < nr)
                    cp16_ef(rb + tid * 16, rbf4 + (size_t)base * 6 + tid, pol);
                if (tid + THREADS < nr)
                    cp16_ef(rb + (tid + THREADS) * 16,
                            rbf4 + (size_t)base * 6 + tid + THREADS, pol);
                if (tid < ts)
                    cp16_ef(ib + tid * 16, idx4 + base + tid, pol);
            }
            cp_commit();
        };

        // ---- x preload for this warp's first group ----
        int g0 = C0 + w;
        float4 a0, a1, a2, a3;
        if (g0 < C1) {
            a0 = __ldcs(x4 + (size_t)(4 * g0 + 0) * 32 + lane);
            a1 = __ldcs(x4 + (size_t)(4 * g0 + 1) * 32 + lane);
            a2 = __ldcs(x4 + (size_t)(4 * g0 + 2) * 32 + lane);
            a3 = __ldcs(x4 + (size_t)(4 * g0 + 3) * 32 + lane);
        }

        issue_tile(0);

        for (int t = 0; t < ntiles; ++t) {
            issue_tile(t + 1);
            cp_wait1();               // tile t complete (t+1 still pending)
            __syncthreads();

            const int bb   = t & 1;
            const int base = C0 + t * TILE_G;

#pragma unroll
            for (int j = 0; j < 8; ++j) {
                const int g  = base + 4 * j + w;     // == C0 + w + 4*(8t+j)
                const int gn = g + 4;                // warp's next group
                const bool vc = (g  < C1);
                const bool vn = (gn < C1);

                // prefetch next group's x rows (2KB in flight)
                float4 b0 = a0, b1 = a1, b2 = a2, b3 = a3;
                if (vn) {
                    b0 = __ldcs(x4 + (size_t)(4 * gn + 0) * 32 + lane);
                    b1 = __ldcs(x4 + (size_t)(4 * gn + 1) * 32 + lane);
                    b2 = __ldcs(x4 + (size_t)(4 * gn + 2) * 32 + lane);
                    b3 = __ldcs(x4 + (size_t)(4 * gn + 3) * 32 + lane);
                }

                if (vc) {
                    const int lg = g - base;
                    const float4* q = &sRbf[bb][lg * 6];
                    int4 nd = sIdx[bb][lg];

                    // edge0: rbf floats 0..5 = q0.xyzw, q1.xy
                    {
                        float4 q0 = q[0], q1 = q[1];
                        float c0 = fmaf(q0.x,w00,fmaf(q0.y,w01,fmaf(q0.z,w02,
                                   fmaf(q0.w,w03,fmaf(q1.x,w04,q1.y*w05)))));
                        float c1 = fmaf(q0.x,w10,fmaf(q0.y,w11,fmaf(q0.z,w12,
                                   fmaf(q0.w,w13,fmaf(q1.x,w14,q1.y*w15)))));
                        float c2 = fmaf(q0.x,w20,fmaf(q0.y,w21,fmaf(q0.z,w22,
                                   fmaf(q0.w,w23,fmaf(q1.x,w24,q1.y*w25)))));
                        float c3 = fmaf(q0.x,w30,fmaf(q0.y,w31,fmaf(q0.z,w32,
                                   fmaf(q0.w,w33,fmaf(q1.x,w34,q1.y*w35)))));
                        float* dst = out + (size_t)nd.x * HIDDEN + hbase;
                        asm volatile("red.global.add.v4.f32 [%0], {%1,%2,%3,%4};"
                                     :: "l"(dst), "f"(c0*a0.x), "f"(c1*a0.y),
                                        "f"(c2*a0.z), "f"(c3*a0.w) : "memory");
                        // edge1: rbf floats 6..11 = q1.zw, q2.xyzw
                        float4 q2 = q[2];
                        float d0 = fmaf(q1.z,w00,fmaf(q1.w,w01,fmaf(q2.x,w02,
                                   fmaf(q2.y,w03,fmaf(q2.z,w04,q2.w*w05)))));
                        float d1 = fmaf(q1.z,w10,fmaf(q1.w,w11,fmaf(q2.x,w12,
                                   fmaf(q2.y,w13,fmaf(q2.z,w14,q2.w*w15)))));
                        float d2 = fmaf(q1.z,w20,fmaf(q1.w,w21,fmaf(q2.x,w22,
                                   fmaf(q2.y,w23,fmaf(q2.z,w24,q2.w*w25)))));
                        float d3 = fmaf(q1.z,w30,fmaf(q1.w,w31,fmaf(q2.x,w32,
                                   fmaf(q2.y,w33,fmaf(q2.z,w34,q2.w*w35)))));
                        float* dst1 = out + (size_t)nd.y * HIDDEN + hbase;
                        asm volatile("red.global.add.v4.f32 [%0], {%1,%2,%3,%4};"
                                     :: "l"(dst1), "f"(d0*a1.x), "f"(d1*a1.y),
                                        "f"(d2*a1.z), "f"(d3*a1.w) : "memory");
                    }
                    // edge2: rbf floats 12..17 = q3.xyzw, q4.xy
                    {
                        float4 q3 = q[3], q4 = q[4];
                        float c0 = fmaf(q3.x,w00,fmaf(q3.y,w01,fmaf(q3.z,w02,
                                   fmaf(q3.w,w03,fmaf(q4.x,w04,q4.y*w05)))));
                        float c1 = fmaf(q3.x,w10,fmaf(q3.y,w11,fmaf(q3.z,w12,
                                   fmaf(q3.w,w13,fmaf(q4.x,w14,q4.y*w15)))));
                        float c2 = fmaf(q3.x,w20,fmaf(q3.y,w21,fmaf(q3.z,w22,
                                   fmaf(q3.w,w23,fmaf(q4.x,w24,q4.y*w25)))));
                        float c3 = fmaf(q3.x,w30,fmaf(q3.y,w31,fmaf(q3.z,w32,
                                   fmaf(q3.w,w33,fmaf(q4.x,w34,q4.y*w35)))));
                        float* dst = out + (size_t)nd.z * HIDDEN + hbase;
                        asm volatile("red.global.add.v4.f32 [%0], {%1,%2,%3,%4};"
                                     :: "l"(dst), "f"(c0*a2.x), "f"(c1*a2.y),
                                        "f"(c2*a2.z), "f"(c3*a2.w) : "memory");
                        // edge3: rbf floats 18..23 = q4.zw, q5.xyzw
                        float4 q5 = q[5];
                        float d0 = fmaf(q4.z,w00,fmaf(q4.w,w01,fmaf(q5.x,w02,
                                   fmaf(q5.y,w03,fmaf(q5.z,w04,q5.w*w05)))));
                        float d1 = fmaf(q4.z,w10,fmaf(q4.w,w11,fmaf(q5.x,w12,
                                   fmaf(q5.y,w13,fmaf(q5.z,w14,q5.w*w15)))));
                        float d2 = fmaf(q4.z,w20,fmaf(q4.w,w21,fmaf(q5.x,w22,
                                   fmaf(q5.y,w23,fmaf(q5.z,w24,q5.w*w25)))));
                        float d3 = fmaf(q4.z,w30,fmaf(q4.w,w31,fmaf(q5.x,w32,
                                   fmaf(q5.y,w33,fmaf(q5.z,w34,q5.w*w35)))));
                        float* dst1 = out + (size_t)nd.w * HIDDEN + hbase;
                        asm volatile("red.global.add.v4.f32 [%0], {%1,%2,%3,%4};"
                                     :: "l"(dst1), "f"(d0*a3.x), "f"(d1*a3.y),
                                        "f"(d2*a3.z), "f"(d3*a3.w) : "memory");
                    }
                }
                a0 = b0; a1 = b1; a2 = b2; a3 = b3;
            }
            __syncthreads();
        }
    }

    // ---- tail edges (E % 4): block 0, warp 0 ----
    if ((E & 3) && blockIdx.x == 0 && w == 0) {
        for (int e = E & ~3; e < E; ++e) {
            int node = idx[e];
            const float2* r2 = reinterpret_cast<const float2*>(rbf) + 3 * (size_t)e;
            float2 g0 = r2[0], g1 = r2[1], g2 = r2[2];
            float4 xv = x4[(size_t)e * 32 + lane];

            float c0 = fmaf(g0.x,w00,fmaf(g0.y,w01,fmaf(g1.x,w02,
                       fmaf(g1.y,w03,fmaf(g2.x,w04,g2.y*w05)))));
            float c1 = fmaf(g0.x,w10,fmaf(g0.y,w11,fmaf(g1.x,w12,
                       fmaf(g1.y,w13,fmaf(g2.x,w14,g2.y*w15)))));
            float c2 = fmaf(g0.x,w20,fmaf(g0.y,w21,fmaf(g1.x,w22,
                       fmaf(g1.y,w23,fmaf(g2.x,w24,g2.y*w25)))));
            float c3 = fmaf(g0.x,w30,fmaf(g0.y,w31,fmaf(g1.x,w32,
                       fmaf(g1.y,w33,fmaf(g2.x,w34,g2.y*w35)))));

            float* dst = out + (size_t)node * HIDDEN + hbase;
            asm volatile("red.global.add.v4.f32 [%0], {%1,%2,%3,%4};"
                         :: "l"(dst), "f"(c0*xv.x), "f"(c1*xv.y),
                            "f"(c2*xv.z), "f"(c3*xv.w) : "memory");
        }
    }
}

extern "C" void kernel_launch(void* const* d_in, const int* in_sizes, int n_in,
                              void* d_out, int out_size)
{
    const float* x   = (const float*)d_in[0];   // [E, 128]
    const float* rbf = (const float*)d_in[1];   // [E, 6]
    const float* W   = (const float*)d_in[2];   // [128, 6]
    const int*   idx = (const int*)d_in[3];     // [E] int32
    float*       out = (float*)d_out;           // [num_nodes, 128]

    const int E = in_sizes[0] / HIDDEN;

    // Zero output (poisoned to 0xAA by harness)
    {
        int n4 = out_size / 4;
        int threads = 256;
        int blocks = (n4 + threads - 1) / threads;
        if (blocks > 8192) blocks = 8192;
        zero_out_kernel<<<blocks, threads>>>((float4*)out, n4);
    }

    // Fused compute + scatter-add
    {
        int G = E >> 2;
        int blocks = 148 * 6;               // persistent CTAs, 6/SM
        int max_blocks = G > 0 ? G : 1;     // >=1 block (tail-only case)
        if (blocks > max_blocks) blocks = max_blocks;
        fused_rbf_scatter_kernel<<<blocks, THREADS>>>(x, rbf, W, idx, out, E);
    }
}